// round 11
// baseline (speedup 1.0000x reference)
#include <cuda_runtime.h>
#include <cstdint>

#define KK   27
#define TPB  96
#define NPB  96             // nodes per block: 32 per warp, 3 warps

typedef unsigned long long ull;

// ---- packed f32x2 helpers ----
__device__ __forceinline__ ull splat2(float v) {
    ull r; asm("mov.b64 %0, {%1, %1};" : "=l"(r) : "f"(v)); return r;
}
__device__ __forceinline__ ull pack2(float lo, float hi) {
    ull r; asm("mov.b64 %0, {%1, %2};" : "=l"(r) : "f"(lo), "f"(hi)); return r;
}
__device__ __forceinline__ void ffma2(ull& d, ull a, ull b) {
    asm("fma.rn.f32x2 %0, %1, %2, %0;" : "+l"(d) : "l"(a), "l"(b));
}
__device__ __forceinline__ ull addp2(ull a, ull b) {
    ull r; asm("add.rn.f32x2 %0, %1, %2;" : "=l"(r) : "l"(a), "l"(b)); return r;
}
__device__ __forceinline__ float getf(const float4& v, int j) {
    switch (j) { case 0: return v.x; case 1: return v.y;
                 case 2: return v.z; default: return v.w; }
}

// Y[i][o] = bias[o] + sum_k sum_c X[nbr[i][k]][c] * W[k][c][o]
//
// Lane l: m = l&3 (channel-quad), h = (l>>2)&1 (output-half), ns = l>>3
// (node octet). Lane accumulates partials over channels [4m,4m+4) x outputs
// [8h,8h+8) for 8 nodes. Weight smem: conflict-free 16B-stride lane classes.
// Gather via __ldcg (L2-resident x; no L1 fills).
//
// R11: occupancy 16 -> 18 warps/SM (TPB=96 x 6 blocks, 113-reg cap);
// traffic is at the decomposition's structural floor, the remaining gap is
// latency exposure. Weight staging vectorized (float4) to shrink prologue.

__global__ __launch_bounds__(TPB, 6)
void conv_kernel(const float* __restrict__ x,       // [N_in, 16]
                 const float* __restrict__ w,       // [27, 16, 16]
                 const float* __restrict__ bias,    // [16]
                 const int*   __restrict__ nbr,     // [N_out, 27]
                 float*       __restrict__ out,     // [N_out, 16]
                 int n_out,
                 const int*   __restrict__ lvl,
                 long long tail_start, int tail_count)
{
    __shared__ __align__(16) float ws[KK * 256];    // 27648 B, permuted
    __shared__ __align__(16) int idxT[KK * NPB];    // 10368 B, [k][node]

    // tail passthrough for flattened (out, level) tuple
    if (blockIdx.x == 0 && lvl != nullptr)
        for (int i = threadIdx.x; i < tail_count; i += TPB)
            out[tail_start + i] = (float)(*lvl);

    // Stage weights permuted (conflict-free 16B-stride lane classes), float4:
    //   scalar map: i = k*256 + c*16 + o; jj=c&3, q=(c>>2)+4*(o>>3), e=o&7
    //   ws[k*256 + jj*64 + (e>>2)*32 + q*4 + (e&3)] = w[i]
    {
        const float4* w4 = reinterpret_cast<const float4*>(w);
        for (int i4 = threadIdx.x; i4 < KK * 64; i4 += TPB) {
            int k = i4 >> 6, rem = i4 & 63;
            int c = rem >> 2, o4 = rem & 3;
            float4 v = __ldg(&w4[i4]);
            int q = (c >> 2) + 4 * (o4 >> 1);
            int dst = k * 256 + (c & 3) * 64 + (o4 & 1) * 32 + q * 4;
            *reinterpret_cast<float4*>(ws + dst) = v;
        }
    }
    // Stage indices transposed: idxT[k][node_local] (coalesced gmem reads)
    const int base = blockIdx.x * NPB;
    for (int i = threadIdx.x; i < KK * NPB; i += TPB) {
        int nl = i / KK, kk = i - nl * KK;
        int node = base + nl;
        if (node >= n_out) node = n_out - 1;
        idxT[kk * NPB + nl] = __ldcg(&nbr[(long long)node * KK + kk]);
    }
    __syncthreads();

    const int warp = threadIdx.x >> 5;
    const int lane = threadIdx.x & 31;
    const int warpbase = base + warp * 32;
    if (warpbase >= n_out) return;
    const int m  = lane & 3;
    const int h  = (lane >> 2) & 1;
    const int ns = lane >> 3;
    const int nlb = warp * 32 + ns * 8;             // local node base (8)
    const int q4 = (m + 4 * h) * 4;                 // lane-class float offset

    ull acc[8][4];                                   // [node][out-pair]
#pragma unroll
    for (int j = 0; j < 8; ++j)
#pragma unroll
        for (int p = 0; p < 4; ++p) acc[j][p] = 0ull;

    // indices for k=0
    int4 ia = *reinterpret_cast<const int4*>(idxT + nlb);
    int4 ib = *reinterpret_cast<const int4*>(idxT + nlb + 4);

#pragma unroll 1
    for (int k = 0; k < KK; ++k) {
        // issue this k's 8 gathers (MLP=8, L2-only)
        float4 xc[8];
        xc[0] = __ldcg(reinterpret_cast<const float4*>(x + (size_t)ia.x * 16) + m);
        xc[1] = __ldcg(reinterpret_cast<const float4*>(x + (size_t)ia.y * 16) + m);
        xc[2] = __ldcg(reinterpret_cast<const float4*>(x + (size_t)ia.z * 16) + m);
        xc[3] = __ldcg(reinterpret_cast<const float4*>(x + (size_t)ia.w * 16) + m);
        xc[4] = __ldcg(reinterpret_cast<const float4*>(x + (size_t)ib.x * 16) + m);
        xc[5] = __ldcg(reinterpret_cast<const float4*>(x + (size_t)ib.y * 16) + m);
        xc[6] = __ldcg(reinterpret_cast<const float4*>(x + (size_t)ib.z * 16) + m);
        xc[7] = __ldcg(reinterpret_cast<const float4*>(x + (size_t)ib.w * 16) + m);

        // prefetch next k's indices (LDS latency hides under compute)
        const int kn = (k + 1 < KK) ? (k + 1) : (KK - 1);
        ia = *reinterpret_cast<const int4*>(idxT + kn * NPB + nlb);
        ib = *reinterpret_cast<const int4*>(idxT + kn * NPB + nlb + 4);

        const float* wk = ws + k * 256 + q4;

        // pass 0: channels jj = 0,1 ; j-outer so first FFMA needs only xc[0]
        {
            ulonglong2 wA0 = *reinterpret_cast<const ulonglong2*>(wk);
            ulonglong2 wB0 = *reinterpret_cast<const ulonglong2*>(wk + 32);
            ulonglong2 wA1 = *reinterpret_cast<const ulonglong2*>(wk + 64);
            ulonglong2 wB1 = *reinterpret_cast<const ulonglong2*>(wk + 96);
#pragma unroll
            for (int j = 0; j < 8; ++j) {
                const ull a0 = splat2(getf(xc[j], 0));
                ffma2(acc[j][0], a0, wA0.x);
                ffma2(acc[j][1], a0, wA0.y);
                ffma2(acc[j][2], a0, wB0.x);
                ffma2(acc[j][3], a0, wB0.y);
                const ull a1 = splat2(getf(xc[j], 1));
                ffma2(acc[j][0], a1, wA1.x);
                ffma2(acc[j][1], a1, wA1.y);
                ffma2(acc[j][2], a1, wB1.x);
                ffma2(acc[j][3], a1, wB1.y);
            }
        }
        // pass 1: channels jj = 2,3
        {
            ulonglong2 wA2 = *reinterpret_cast<const ulonglong2*>(wk + 128);
            ulonglong2 wB2 = *reinterpret_cast<const ulonglong2*>(wk + 160);
            ulonglong2 wA3 = *reinterpret_cast<const ulonglong2*>(wk + 192);
            ulonglong2 wB3 = *reinterpret_cast<const ulonglong2*>(wk + 224);
#pragma unroll
            for (int j = 0; j < 8; ++j) {
                const ull a2 = splat2(getf(xc[j], 2));
                ffma2(acc[j][0], a2, wA2.x);
                ffma2(acc[j][1], a2, wA2.y);
                ffma2(acc[j][2], a2, wB2.x);
                ffma2(acc[j][3], a2, wB2.y);
                const ull a3 = splat2(getf(xc[j], 3));
                ffma2(acc[j][0], a3, wA3.x);
                ffma2(acc[j][1], a3, wA3.y);
                ffma2(acc[j][2], a3, wB3.x);
                ffma2(acc[j][3], a3, wB3.y);
            }
        }
    }

    // Epilogue: reduce channel-quad partials over the 4 m-lanes, add bias.
    float4 b0 = __ldg(reinterpret_cast<const float4*>(bias) + 2 * h);
    float4 b1 = __ldg(reinterpret_cast<const float4*>(bias) + 2 * h + 1);
    ull bp[4] = { pack2(b0.x, b0.y), pack2(b0.z, b0.w),
                  pack2(b1.x, b1.y), pack2(b1.z, b1.w) };

#pragma unroll
    for (int j = 0; j < 8; ++j) {
#pragma unroll
        for (int p = 0; p < 4; ++p) {
            ull v = acc[j][p];
            v = addp2(v, __shfl_xor_sync(0xffffffffu, v, 1));
            v = addp2(v, __shfl_xor_sync(0xffffffffu, v, 2));
            acc[j][p] = v;
        }
        const int node = warpbase + ns * 8 + j;
        if (m == 0 && node < n_out) {
            ulonglong2* op = reinterpret_cast<ulonglong2*>(
                out + (long long)node * 16 + 8 * h);
            ulonglong2 s0; s0.x = addp2(acc[j][0], bp[0]);
                           s0.y = addp2(acc[j][1], bp[1]);
            ulonglong2 s1; s1.x = addp2(acc[j][2], bp[2]);
                           s1.y = addp2(acc[j][3], bp[3]);
            op[0] = s0;
            op[1] = s1;
        }
    }
}

extern "C" void kernel_launch(void* const* d_in, const int* in_sizes, int n_in,
                              void* d_out, int out_size)
{
    const float* x    = (const float*)d_in[0];
    const float* w    = (const float*)d_in[1];
    const float* bias = (const float*)d_in[2];
    const int*   nbr  = (const int*)d_in[3];
    const int*   lvl  = (n_in > 4) ? (const int*)d_in[4] : nullptr;

    const int n_out = in_sizes[3] / KK;
    float* out = (float*)d_out;

    const long long conv_elems = (long long)n_out * 16;
    long long tail_start = conv_elems;
    int tail_count = 0;
    if ((long long)out_size > conv_elems && lvl != nullptr)
        tail_count = (int)((long long)out_size - conv_elems);

    const int grid = (n_out + NPB - 1) / NPB;
    conv_kernel<<<grid, TPB>>>(x, w, bias, nbr, out, n_out,
                               lvl, tail_start, tail_count);
}

// round 12
// speedup vs baseline: 1.9713x; 1.9713x over previous
#include <cuda_runtime.h>
#include <cstdint>

#define KK   27
#define TPB  256
#define NPB  256            // nodes per block: 32 per warp, 8 warps

typedef unsigned long long ull;

// ---- packed f32x2 helpers ----
__device__ __forceinline__ ull splat2(float v) {
    ull r; asm("mov.b64 %0, {%1, %1};" : "=l"(r) : "f"(v)); return r;
}
__device__ __forceinline__ ull pack2(float lo, float hi) {
    ull r; asm("mov.b64 %0, {%1, %2};" : "=l"(r) : "f"(lo), "f"(hi)); return r;
}
__device__ __forceinline__ void ffma2(ull& d, ull a, ull b) {
    asm("fma.rn.f32x2 %0, %1, %2, %0;" : "+l"(d) : "l"(a), "l"(b));
}
__device__ __forceinline__ ull addp2(ull a, ull b) {
    ull r; asm("add.rn.f32x2 %0, %1, %2;" : "=l"(r) : "l"(a), "l"(b)); return r;
}
__device__ __forceinline__ float getf(const float4& v, int j) {
    switch (j) { case 0: return v.x; case 1: return v.y;
                 case 2: return v.z; default: return v.w; }
}

// Y[i][o] = bias[o] + sum_k sum_c X[nbr[i][k]][c] * W[k][c][o]
//
// Decomposition (proven R8-R10): lane l -> m = l&3 (channel-quad),
// h = (l>>2)&1 (output-half), ns = l>>3 (node octet); lane accumulates
// partials over channels [4m,4m+4) x outputs [8h,8h+8) for 8 nodes.
// Weight smem: conflict-free 16B-stride lane classes. Gather via __ldcg
// (x L2-resident; no L1 fills). 128-reg/16-warp ceiling is hard (regfile);
// any launch_bounds tighter than (256,2) spills into the mainloop (R11).
//
// R12: TPB/NPB 128 -> 256 (same 16 warps/SM, 2 blocks): halves per-block
// weight/idx staging overhead (~13% of the binding LSU budget) and wave
// count; mainloop byte-identical to R10.

__global__ __launch_bounds__(TPB, 2)
void conv_kernel(const float* __restrict__ x,       // [N_in, 16]
                 const float* __restrict__ w,       // [27, 16, 16]
                 const float* __restrict__ bias,    // [16]
                 const int*   __restrict__ nbr,     // [N_out, 27]
                 float*       __restrict__ out,     // [N_out, 16]
                 int n_out,
                 const int*   __restrict__ lvl,
                 long long tail_start, int tail_count)
{
    __shared__ __align__(16) float ws[KK * 256];    // 27648 B, permuted
    __shared__ __align__(16) int idxT[KK * NPB];    // 27648 B, [k][node]

    // tail passthrough for flattened (out, level) tuple
    if (blockIdx.x == 0 && lvl != nullptr)
        for (int i = threadIdx.x; i < tail_count; i += TPB)
            out[tail_start + i] = (float)(*lvl);

    // Stage weights permuted (conflict-free 16B-stride lane classes), float4:
    //   scalar map: i = k*256 + c*16 + o; jj=c&3, q=(c>>2)+4*(o>>3), e=o&7
    //   ws[k*256 + jj*64 + (e>>2)*32 + q*4 + (e&3)] = w[i]
    {
        const float4* w4 = reinterpret_cast<const float4*>(w);
        for (int i4 = threadIdx.x; i4 < KK * 64; i4 += TPB) {
            int k = i4 >> 6, rem = i4 & 63;
            int c = rem >> 2, o4 = rem & 3;
            float4 v = __ldg(&w4[i4]);
            int q = (c >> 2) + 4 * (o4 >> 1);
            int dst = k * 256 + (c & 3) * 64 + (o4 & 1) * 32 + q * 4;
            *reinterpret_cast<float4*>(ws + dst) = v;
        }
    }
    // Stage indices transposed: idxT[k][node_local] (coalesced gmem reads)
    const int base = blockIdx.x * NPB;
    for (int i = threadIdx.x; i < KK * NPB; i += TPB) {
        int nl = i / KK, kk = i - nl * KK;
        int node = base + nl;
        if (node >= n_out) node = n_out - 1;
        idxT[kk * NPB + nl] = __ldcg(&nbr[(long long)node * KK + kk]);
    }
    __syncthreads();

    const int warp = threadIdx.x >> 5;
    const int lane = threadIdx.x & 31;
    const int warpbase = base + warp * 32;
    if (warpbase >= n_out) return;
    const int m  = lane & 3;
    const int h  = (lane >> 2) & 1;
    const int ns = lane >> 3;
    const int nlb = warp * 32 + ns * 8;             // local node base (8)
    const int q4 = (m + 4 * h) * 4;                 // lane-class float offset

    ull acc[8][4];                                   // [node][out-pair]
#pragma unroll
    for (int j = 0; j < 8; ++j)
#pragma unroll
        for (int p = 0; p < 4; ++p) acc[j][p] = 0ull;

    // indices for k=0
    int4 ia = *reinterpret_cast<const int4*>(idxT + nlb);
    int4 ib = *reinterpret_cast<const int4*>(idxT + nlb + 4);

#pragma unroll 1
    for (int k = 0; k < KK; ++k) {
        // issue this k's 8 gathers (MLP=8, L2-only)
        float4 xc[8];
        xc[0] = __ldcg(reinterpret_cast<const float4*>(x + (size_t)ia.x * 16) + m);
        xc[1] = __ldcg(reinterpret_cast<const float4*>(x + (size_t)ia.y * 16) + m);
        xc[2] = __ldcg(reinterpret_cast<const float4*>(x + (size_t)ia.z * 16) + m);
        xc[3] = __ldcg(reinterpret_cast<const float4*>(x + (size_t)ia.w * 16) + m);
        xc[4] = __ldcg(reinterpret_cast<const float4*>(x + (size_t)ib.x * 16) + m);
        xc[5] = __ldcg(reinterpret_cast<const float4*>(x + (size_t)ib.y * 16) + m);
        xc[6] = __ldcg(reinterpret_cast<const float4*>(x + (size_t)ib.z * 16) + m);
        xc[7] = __ldcg(reinterpret_cast<const float4*>(x + (size_t)ib.w * 16) + m);

        // prefetch next k's indices (LDS latency hides under compute)
        const int kn = (k + 1 < KK) ? (k + 1) : (KK - 1);
        ia = *reinterpret_cast<const int4*>(idxT + kn * NPB + nlb);
        ib = *reinterpret_cast<const int4*>(idxT + kn * NPB + nlb + 4);

        const float* wk = ws + k * 256 + q4;

        // pass 0: channels jj = 0,1 ; j-outer so first FFMA needs only xc[0]
        {
            ulonglong2 wA0 = *reinterpret_cast<const ulonglong2*>(wk);
            ulonglong2 wB0 = *reinterpret_cast<const ulonglong2*>(wk + 32);
            ulonglong2 wA1 = *reinterpret_cast<const ulonglong2*>(wk + 64);
            ulonglong2 wB1 = *reinterpret_cast<const ulonglong2*>(wk + 96);
#pragma unroll
            for (int j = 0; j < 8; ++j) {
                const ull a0 = splat2(getf(xc[j], 0));
                ffma2(acc[j][0], a0, wA0.x);
                ffma2(acc[j][1], a0, wA0.y);
                ffma2(acc[j][2], a0, wB0.x);
                ffma2(acc[j][3], a0, wB0.y);
                const ull a1 = splat2(getf(xc[j], 1));
                ffma2(acc[j][0], a1, wA1.x);
                ffma2(acc[j][1], a1, wA1.y);
                ffma2(acc[j][2], a1, wB1.x);
                ffma2(acc[j][3], a1, wB1.y);
            }
        }
        // pass 1: channels jj = 2,3
        {
            ulonglong2 wA2 = *reinterpret_cast<const ulonglong2*>(wk + 128);
            ulonglong2 wB2 = *reinterpret_cast<const ulonglong2*>(wk + 160);
            ulonglong2 wA3 = *reinterpret_cast<const ulonglong2*>(wk + 192);
            ulonglong2 wB3 = *reinterpret_cast<const ulonglong2*>(wk + 224);
#pragma unroll
            for (int j = 0; j < 8; ++j) {
                const ull a2 = splat2(getf(xc[j], 2));
                ffma2(acc[j][0], a2, wA2.x);
                ffma2(acc[j][1], a2, wA2.y);
                ffma2(acc[j][2], a2, wB2.x);
                ffma2(acc[j][3], a2, wB2.y);
                const ull a3 = splat2(getf(xc[j], 3));
                ffma2(acc[j][0], a3, wA3.x);
                ffma2(acc[j][1], a3, wA3.y);
                ffma2(acc[j][2], a3, wB3.x);
                ffma2(acc[j][3], a3, wB3.y);
            }
        }
    }

    // Epilogue: reduce channel-quad partials over the 4 m-lanes, add bias.
    float4 b0 = __ldg(reinterpret_cast<const float4*>(bias) + 2 * h);
    float4 b1 = __ldg(reinterpret_cast<const float4*>(bias) + 2 * h + 1);
    ull bp[4] = { pack2(b0.x, b0.y), pack2(b0.z, b0.w),
                  pack2(b1.x, b1.y), pack2(b1.z, b1.w) };

#pragma unroll
    for (int j = 0; j < 8; ++j) {
#pragma unroll
        for (int p = 0; p < 4; ++p) {
            ull v = acc[j][p];
            v = addp2(v, __shfl_xor_sync(0xffffffffu, v, 1));
            v = addp2(v, __shfl_xor_sync(0xffffffffu, v, 2));
            acc[j][p] = v;
        }
        const int node = warpbase + ns * 8 + j;
        if (m == 0 && node < n_out) {
            ulonglong2* op = reinterpret_cast<ulonglong2*>(
                out + (long long)node * 16 + 8 * h);
            ulonglong2 s0; s0.x = addp2(acc[j][0], bp[0]);
                           s0.y = addp2(acc[j][1], bp[1]);
            ulonglong2 s1; s1.x = addp2(acc[j][2], bp[2]);
                           s1.y = addp2(acc[j][3], bp[3]);
            op[0] = s0;
            op[1] = s1;
        }
    }
}

extern "C" void kernel_launch(void* const* d_in, const int* in_sizes, int n_in,
                              void* d_out, int out_size)
{
    const float* x    = (const float*)d_in[0];
    const float* w    = (const float*)d_in[1];
    const float* bias = (const float*)d_in[2];
    const int*   nbr  = (const int*)d_in[3];
    const int*   lvl  = (n_in > 4) ? (const int*)d_in[4] : nullptr;

    const int n_out = in_sizes[3] / KK;
    float* out = (float*)d_out;

    const long long conv_elems = (long long)n_out * 16;
    long long tail_start = conv_elems;
    int tail_count = 0;
    if ((long long)out_size > conv_elems && lvl != nullptr)
        tail_count = (int)((long long)out_size - conv_elems);

    const int grid = (n_out + NPB - 1) / NPB;
    conv_kernel<<<grid, TPB>>>(x, w, bias, nbr, out, n_out,
                               lvl, tail_start, tail_count);
}

// round 13
// speedup vs baseline: 1.9797x; 1.0043x over previous
#include <cuda_runtime.h>
#include <cstdint>

#define KK   27
#define TPB  128
#define NPB  128            // nodes per block: 32 per warp, 4 warps

typedef unsigned long long ull;

// ---- packed f32x2 helpers ----
__device__ __forceinline__ ull splat2(float v) {
    ull r; asm("mov.b64 %0, {%1, %1};" : "=l"(r) : "f"(v)); return r;
}
__device__ __forceinline__ ull pack2(float lo, float hi) {
    ull r; asm("mov.b64 %0, {%1, %2};" : "=l"(r) : "f"(lo), "f"(hi)); return r;
}
__device__ __forceinline__ void ffma2(ull& d, ull a, ull b) {
    asm("fma.rn.f32x2 %0, %1, %2, %0;" : "+l"(d) : "l"(a), "l"(b));
}
__device__ __forceinline__ ull addp2(ull a, ull b) {
    ull r; asm("add.rn.f32x2 %0, %1, %2;" : "=l"(r) : "l"(a), "l"(b)); return r;
}
__device__ __forceinline__ float getf(const float4& v, int j) {
    switch (j) { case 0: return v.x; case 1: return v.y;
                 case 2: return v.z; default: return v.w; }
}

// Y[i][o] = bias[o] + sum_k sum_c X[nbr[i][k]][c] * W[k][c][o]
//
// Decomposition (R8-R10): lane l -> m = l&3 (channel-quad), h = (l>>2)&1
// (output-half), ns = l>>3 (node octet); lane holds partials over channels
// [4m,4m+4) x outputs [8h,8h+8) for 8 nodes. Conflict-free weight smem,
// __ldcg gather. 128-reg/16-warp ceiling is hard (R11).
//
// R13: zero-register software pipeline. Each k-iter is split into two
// row-halves; xc[0-3]/xc[4-7] are overwritten with NEXT k's gather right
// after their last FFMA read (WAR recycling), giving each gather ~1/2 to a
// full iteration of lookahead before consumption. Cost: jj01 weight quad
// loaded twice per k (12 vs 8 weight LDS). idx loads just-in-time (LDS
// latency trivially covered), freeing the old prefetch registers.

__global__ __launch_bounds__(TPB, 2)
void conv_kernel(const float* __restrict__ x,       // [N_in, 16]
                 const float* __restrict__ w,       // [27, 16, 16]
                 const float* __restrict__ bias,    // [16]
                 const int*   __restrict__ nbr,     // [N_out, 27]
                 float*       __restrict__ out,     // [N_out, 16]
                 int n_out,
                 const int*   __restrict__ lvl,
                 long long tail_start, int tail_count)
{
    __shared__ __align__(16) float ws[KK * 256];    // 27648 B, permuted
    __shared__ __align__(16) int idxT[KK * NPB];    // 13824 B, [k][node]

    // tail passthrough for flattened (out, level) tuple
    if (blockIdx.x == 0 && lvl != nullptr)
        for (int i = threadIdx.x; i < tail_count; i += TPB)
            out[tail_start + i] = (float)(*lvl);

    // Stage weights permuted (conflict-free 16B-stride lane classes), float4:
    //   scalar map: i = k*256 + c*16 + o; jj=c&3, q=(c>>2)+4*(o>>3), e=o&7
    //   ws[k*256 + jj*64 + (e>>2)*32 + q*4 + (e&3)] = w[i]
    {
        const float4* w4 = reinterpret_cast<const float4*>(w);
        for (int i4 = threadIdx.x; i4 < KK * 64; i4 += TPB) {
            int k = i4 >> 6, rem = i4 & 63;
            int c = rem >> 2, o4 = rem & 3;
            float4 v = __ldg(&w4[i4]);
            int q = (c >> 2) + 4 * (o4 >> 1);
            int dst = k * 256 + (c & 3) * 64 + (o4 & 1) * 32 + q * 4;
            *reinterpret_cast<float4*>(ws + dst) = v;
        }
    }
    // Stage indices transposed: idxT[k][node_local] (coalesced gmem reads)
    const int base = blockIdx.x * NPB;
    for (int i = threadIdx.x; i < KK * NPB; i += TPB) {
        int nl = i / KK, kk = i - nl * KK;
        int node = base + nl;
        if (node >= n_out) node = n_out - 1;
        idxT[kk * NPB + nl] = __ldcg(&nbr[(long long)node * KK + kk]);
    }
    __syncthreads();

    const int warp = threadIdx.x >> 5;
    const int lane = threadIdx.x & 31;
    const int warpbase = base + warp * 32;
    if (warpbase >= n_out) return;
    const int m  = lane & 3;
    const int h  = (lane >> 2) & 1;
    const int ns = lane >> 3;
    const int nlb = warp * 32 + ns * 8;             // local node base (8)
    const int q4 = (m + 4 * h) * 4;                 // lane-class float offset

    ull acc[8][4];                                   // [node][out-pair]
#pragma unroll
    for (int j = 0; j < 8; ++j)
#pragma unroll
        for (int p = 0; p < 4; ++p) acc[j][p] = 0ull;

    // preload k=0: all 8 rows
    float4 xc[8];
    {
        int4 ia = *reinterpret_cast<const int4*>(idxT + nlb);
        int4 ib = *reinterpret_cast<const int4*>(idxT + nlb + 4);
        xc[0] = __ldcg(reinterpret_cast<const float4*>(x + (size_t)ia.x * 16) + m);
        xc[1] = __ldcg(reinterpret_cast<const float4*>(x + (size_t)ia.y * 16) + m);
        xc[2] = __ldcg(reinterpret_cast<const float4*>(x + (size_t)ia.z * 16) + m);
        xc[3] = __ldcg(reinterpret_cast<const float4*>(x + (size_t)ia.w * 16) + m);
        xc[4] = __ldcg(reinterpret_cast<const float4*>(x + (size_t)ib.x * 16) + m);
        xc[5] = __ldcg(reinterpret_cast<const float4*>(x + (size_t)ib.y * 16) + m);
        xc[6] = __ldcg(reinterpret_cast<const float4*>(x + (size_t)ib.z * 16) + m);
        xc[7] = __ldcg(reinterpret_cast<const float4*>(x + (size_t)ib.w * 16) + m);
    }

#pragma unroll 1
    for (int k = 0; k < KK; ++k) {
        const int kn = (k + 1 < KK) ? (k + 1) : (KK - 1);
        const float* wk = ws + k * 256 + q4;

        // idx for next-k rows 0-3 (29-cyc LDS latency covered by phase 1-2)
        int4 ia = *reinterpret_cast<const int4*>(idxT + kn * NPB + nlb);

        // phase 1: rows 0-3 x channels jj=0,1
        {
            ulonglong2 wA0 = *reinterpret_cast<const ulonglong2*>(wk);
            ulonglong2 wB0 = *reinterpret_cast<const ulonglong2*>(wk + 32);
            ulonglong2 wA1 = *reinterpret_cast<const ulonglong2*>(wk + 64);
            ulonglong2 wB1 = *reinterpret_cast<const ulonglong2*>(wk + 96);
#pragma unroll
            for (int j = 0; j < 4; ++j) {
                const ull a0 = splat2(getf(xc[j], 0));
                ffma2(acc[j][0], a0, wA0.x);
                ffma2(acc[j][1], a0, wA0.y);
                ffma2(acc[j][2], a0, wB0.x);
                ffma2(acc[j][3], a0, wB0.y);
                const ull a1 = splat2(getf(xc[j], 1));
                ffma2(acc[j][0], a1, wA1.x);
                ffma2(acc[j][1], a1, wA1.y);
                ffma2(acc[j][2], a1, wB1.x);
                ffma2(acc[j][3], a1, wB1.y);
            }
        }
        // phase 2: rows 0-3 x channels jj=2,3 (B-quad stays live for phase 4)
        ulonglong2 wA2 = *reinterpret_cast<const ulonglong2*>(wk + 128);
        ulonglong2 wB2 = *reinterpret_cast<const ulonglong2*>(wk + 160);
        ulonglong2 wA3 = *reinterpret_cast<const ulonglong2*>(wk + 192);
        ulonglong2 wB3 = *reinterpret_cast<const ulonglong2*>(wk + 224);
#pragma unroll
        for (int j = 0; j < 4; ++j) {
            const ull a2 = splat2(getf(xc[j], 2));
            ffma2(acc[j][0], a2, wA2.x);
            ffma2(acc[j][1], a2, wA2.y);
            ffma2(acc[j][2], a2, wB2.x);
            ffma2(acc[j][3], a2, wB2.y);
            const ull a3 = splat2(getf(xc[j], 3));
            ffma2(acc[j][0], a3, wA3.x);
            ffma2(acc[j][1], a3, wA3.y);
            ffma2(acc[j][2], a3, wB3.x);
            ffma2(acc[j][3], a3, wB3.y);
        }

        // rows 0-3 of k fully consumed -> recycle regs with next-k gather
        xc[0] = __ldcg(reinterpret_cast<const float4*>(x + (size_t)ia.x * 16) + m);
        xc[1] = __ldcg(reinterpret_cast<const float4*>(x + (size_t)ia.y * 16) + m);
        xc[2] = __ldcg(reinterpret_cast<const float4*>(x + (size_t)ia.z * 16) + m);
        xc[3] = __ldcg(reinterpret_cast<const float4*>(x + (size_t)ia.w * 16) + m);

        // idx for next-k rows 4-7
        int4 ib = *reinterpret_cast<const int4*>(idxT + kn * NPB + nlb + 4);

        // phase 3: rows 4-7 x channels jj=0,1 (reload the jj01 quads)
        {
            ulonglong2 wA0 = *reinterpret_cast<const ulonglong2*>(wk);
            ulonglong2 wB0 = *reinterpret_cast<const ulonglong2*>(wk + 32);
            ulonglong2 wA1 = *reinterpret_cast<const ulonglong2*>(wk + 64);
            ulonglong2 wB1 = *reinterpret_cast<const ulonglong2*>(wk + 96);
#pragma unroll
            for (int j = 4; j < 8; ++j) {
                const ull a0 = splat2(getf(xc[j], 0));
                ffma2(acc[j][0], a0, wA0.x);
                ffma2(acc[j][1], a0, wA0.y);
                ffma2(acc[j][2], a0, wB0.x);
                ffma2(acc[j][3], a0, wB0.y);
                const ull a1 = splat2(getf(xc[j], 1));
                ffma2(acc[j][0], a1, wA1.x);
                ffma2(acc[j][1], a1, wA1.y);
                ffma2(acc[j][2], a1, wB1.x);
                ffma2(acc[j][3], a1, wB1.y);
            }
        }
        // phase 4: rows 4-7 x channels jj=2,3 (B-quads still live)
#pragma unroll
        for (int j = 4; j < 8; ++j) {
            const ull a2 = splat2(getf(xc[j], 2));
            ffma2(acc[j][0], a2, wA2.x);
            ffma2(acc[j][1], a2, wA2.y);
            ffma2(acc[j][2], a2, wB2.x);
            ffma2(acc[j][3], a2, wB2.y);
            const ull a3 = splat2(getf(xc[j], 3));
            ffma2(acc[j][0], a3, wA3.x);
            ffma2(acc[j][1], a3, wA3.y);
            ffma2(acc[j][2], a3, wB3.x);
            ffma2(acc[j][3], a3, wB3.y);
        }

        // rows 4-7 consumed -> recycle with next-k gather
        xc[4] = __ldcg(reinterpret_cast<const float4*>(x + (size_t)ib.x * 16) + m);
        xc[5] = __ldcg(reinterpret_cast<const float4*>(x + (size_t)ib.y * 16) + m);
        xc[6] = __ldcg(reinterpret_cast<const float4*>(x + (size_t)ib.z * 16) + m);
        xc[7] = __ldcg(reinterpret_cast<const float4*>(x + (size_t)ib.w * 16) + m);
    }

    // Epilogue: reduce channel-quad partials over the 4 m-lanes, add bias.
    float4 b0 = __ldg(reinterpret_cast<const float4*>(bias) + 2 * h);
    float4 b1 = __ldg(reinterpret_cast<const float4*>(bias) + 2 * h + 1);
    ull bp[4] = { pack2(b0.x, b0.y), pack2(b0.z, b0.w),
                  pack2(b1.x, b1.y), pack2(b1.z, b1.w) };

#pragma unroll
    for (int j = 0; j < 8; ++j) {
#pragma unroll
        for (int p = 0; p < 4; ++p) {
            ull v = acc[j][p];
            v = addp2(v, __shfl_xor_sync(0xffffffffu, v, 1));
            v = addp2(v, __shfl_xor_sync(0xffffffffu, v, 2));
            acc[j][p] = v;
        }
        const int node = warpbase + ns * 8 + j;
        if (m == 0 && node < n_out) {
            ulonglong2* op = reinterpret_cast<ulonglong2*>(
                out + (long long)node * 16 + 8 * h);
            ulonglong2 s0; s0.x = addp2(acc[j][0], bp[0]);
                           s0.y = addp2(acc[j][1], bp[1]);
            ulonglong2 s1; s1.x = addp2(acc[j][2], bp[2]);
                           s1.y = addp2(acc[j][3], bp[3]);
            op[0] = s0;
            op[1] = s1;
        }
    }
}

extern "C" void kernel_launch(void* const* d_in, const int* in_sizes, int n_in,
                              void* d_out, int out_size)
{
    const float* x    = (const float*)d_in[0];
    const float* w    = (const float*)d_in[1];
    const float* bias = (const float*)d_in[2];
    const int*   nbr  = (const int*)d_in[3];
    const int*   lvl  = (n_in > 4) ? (const int*)d_in[4] : nullptr;

    const int n_out = in_sizes[3] / KK;
    float* out = (float*)d_out;

    const long long conv_elems = (long long)n_out * 16;
    long long tail_start = conv_elems;
    int tail_count = 0;
    if ((long long)out_size > conv_elems && lvl != nullptr)
        tail_count = (int)((long long)out_size - conv_elems);

    const int grid = (n_out + NPB - 1) / NPB;
    conv_kernel<<<grid, TPB>>>(x, w, bias, nbr, out, n_out,
                               lvl, tail_start, tail_count);
}

// round 14
// speedup vs baseline: 2.1469x; 1.0845x over previous
#include <cuda_runtime.h>
#include <cstdint>

#define KK   27
#define TPB  128
#define NPB  128            // nodes per block: 32 per warp, 4 warps

typedef unsigned long long ull;

// ---- packed f32x2 helpers ----
__device__ __forceinline__ ull splat2(float v) {
    ull r; asm("mov.b64 %0, {%1, %1};" : "=l"(r) : "f"(v)); return r;
}
__device__ __forceinline__ ull pack2(float lo, float hi) {
    ull r; asm("mov.b64 %0, {%1, %2};" : "=l"(r) : "f"(lo), "f"(hi)); return r;
}
__device__ __forceinline__ void ffma2(ull& d, ull a, ull b) {
    asm("fma.rn.f32x2 %0, %1, %2, %0;" : "+l"(d) : "l"(a), "l"(b));
}
__device__ __forceinline__ ull addp2(ull a, ull b) {
    ull r; asm("add.rn.f32x2 %0, %1, %2;" : "=l"(r) : "l"(a), "l"(b)); return r;
}
__device__ __forceinline__ float getf(const float4& v, int j) {
    switch (j) { case 0: return v.x; case 1: return v.y;
                 case 2: return v.z; default: return v.w; }
}

// Y[i][o] = bias[o] + sum_k sum_c X[nbr[i][k]][c] * W[k][c][o]
//
// Decomposition (R8-R10): lane l -> m = l&3 (channel-quad), h = (l>>2)&1
// (output-half), ns = l>>3 (node octet); lane holds partials over channels
// [4m,4m+4) x outputs [8h,8h+8) for 8 nodes. Conflict-free weight smem,
// __ldcg gather.
//
// R14 = R13's WAR-recycling pipeline (xc halves overwritten with next-k
// gathers right after last read -> each gather has ~1/2..1 iteration of
// lookahead) at R10's 16 warps/SM: launch_bounds(128,4) hard-caps 128 regs
// (R13 accidentally ran (128,2) -> 134 regs -> 12 warps). To fit, phase 4
// reloads wA2/wB2 from smem (+2 LDS/warp-k); only wA3/wB3 stay persistent.

__global__ __launch_bounds__(TPB, 4)
void conv_kernel(const float* __restrict__ x,       // [N_in, 16]
                 const float* __restrict__ w,       // [27, 16, 16]
                 const float* __restrict__ bias,    // [16]
                 const int*   __restrict__ nbr,     // [N_out, 27]
                 float*       __restrict__ out,     // [N_out, 16]
                 int n_out,
                 const int*   __restrict__ lvl,
                 long long tail_start, int tail_count)
{
    __shared__ __align__(16) float ws[KK * 256];    // 27648 B, permuted
    __shared__ __align__(16) int idxT[KK * NPB];    // 13824 B, [k][node]

    // tail passthrough for flattened (out, level) tuple
    if (blockIdx.x == 0 && lvl != nullptr)
        for (int i = threadIdx.x; i < tail_count; i += TPB)
            out[tail_start + i] = (float)(*lvl);

    // Stage weights permuted (conflict-free 16B-stride lane classes), float4:
    //   scalar map: i = k*256 + c*16 + o; jj=c&3, q=(c>>2)+4*(o>>3), e=o&7
    //   ws[k*256 + jj*64 + (e>>2)*32 + q*4 + (e&3)] = w[i]
    {
        const float4* w4 = reinterpret_cast<const float4*>(w);
        for (int i4 = threadIdx.x; i4 < KK * 64; i4 += TPB) {
            int k = i4 >> 6, rem = i4 & 63;
            int c = rem >> 2, o4 = rem & 3;
            float4 v = __ldg(&w4[i4]);
            int q = (c >> 2) + 4 * (o4 >> 1);
            int dst = k * 256 + (c & 3) * 64 + (o4 & 1) * 32 + q * 4;
            *reinterpret_cast<float4*>(ws + dst) = v;
        }
    }
    // Stage indices transposed: idxT[k][node_local] (coalesced gmem reads)
    const int base = blockIdx.x * NPB;
    for (int i = threadIdx.x; i < KK * NPB; i += TPB) {
        int nl = i / KK, kk = i - nl * KK;
        int node = base + nl;
        if (node >= n_out) node = n_out - 1;
        idxT[kk * NPB + nl] = __ldcg(&nbr[(long long)node * KK + kk]);
    }
    __syncthreads();

    const int warp = threadIdx.x >> 5;
    const int lane = threadIdx.x & 31;
    const int warpbase = base + warp * 32;
    if (warpbase >= n_out) return;
    const int m  = lane & 3;
    const int h  = (lane >> 2) & 1;
    const int ns = lane >> 3;
    const int nlb = warp * 32 + ns * 8;             // local node base (8)
    const int q4 = (m + 4 * h) * 4;                 // lane-class float offset

    ull acc[8][4];                                   // [node][out-pair]
#pragma unroll
    for (int j = 0; j < 8; ++j)
#pragma unroll
        for (int p = 0; p < 4; ++p) acc[j][p] = 0ull;

    // preload k=0: all 8 rows
    float4 xc[8];
    {
        int4 ia = *reinterpret_cast<const int4*>(idxT + nlb);
        int4 ib = *reinterpret_cast<const int4*>(idxT + nlb + 4);
        xc[0] = __ldcg(reinterpret_cast<const float4*>(x + (size_t)ia.x * 16) + m);
        xc[1] = __ldcg(reinterpret_cast<const float4*>(x + (size_t)ia.y * 16) + m);
        xc[2] = __ldcg(reinterpret_cast<const float4*>(x + (size_t)ia.z * 16) + m);
        xc[3] = __ldcg(reinterpret_cast<const float4*>(x + (size_t)ia.w * 16) + m);
        xc[4] = __ldcg(reinterpret_cast<const float4*>(x + (size_t)ib.x * 16) + m);
        xc[5] = __ldcg(reinterpret_cast<const float4*>(x + (size_t)ib.y * 16) + m);
        xc[6] = __ldcg(reinterpret_cast<const float4*>(x + (size_t)ib.z * 16) + m);
        xc[7] = __ldcg(reinterpret_cast<const float4*>(x + (size_t)ib.w * 16) + m);
    }

#pragma unroll 1
    for (int k = 0; k < KK; ++k) {
        const int kn = (k + 1 < KK) ? (k + 1) : (KK - 1);
        const float* wk = ws + k * 256 + q4;

        // idx for next-k rows 0-3 (29-cyc LDS latency covered by phase 1-2)
        int4 ia = *reinterpret_cast<const int4*>(idxT + kn * NPB + nlb);

        // phase 1: rows 0-3 x channels jj=0,1
        {
            ulonglong2 wA0 = *reinterpret_cast<const ulonglong2*>(wk);
            ulonglong2 wB0 = *reinterpret_cast<const ulonglong2*>(wk + 32);
            ulonglong2 wA1 = *reinterpret_cast<const ulonglong2*>(wk + 64);
            ulonglong2 wB1 = *reinterpret_cast<const ulonglong2*>(wk + 96);
#pragma unroll
            for (int j = 0; j < 4; ++j) {
                const ull a0 = splat2(getf(xc[j], 0));
                ffma2(acc[j][0], a0, wA0.x);
                ffma2(acc[j][1], a0, wA0.y);
                ffma2(acc[j][2], a0, wB0.x);
                ffma2(acc[j][3], a0, wB0.y);
                const ull a1 = splat2(getf(xc[j], 1));
                ffma2(acc[j][0], a1, wA1.x);
                ffma2(acc[j][1], a1, wA1.y);
                ffma2(acc[j][2], a1, wB1.x);
                ffma2(acc[j][3], a1, wB1.y);
            }
        }
        // phase 2: rows 0-3 x channels jj=2,3 (only wA3/wB3 stay persistent)
        ulonglong2 wA3 = *reinterpret_cast<const ulonglong2*>(wk + 192);
        ulonglong2 wB3 = *reinterpret_cast<const ulonglong2*>(wk + 224);
        {
            ulonglong2 wA2 = *reinterpret_cast<const ulonglong2*>(wk + 128);
            ulonglong2 wB2 = *reinterpret_cast<const ulonglong2*>(wk + 160);
#pragma unroll
            for (int j = 0; j < 4; ++j) {
                const ull a2 = splat2(getf(xc[j], 2));
                ffma2(acc[j][0], a2, wA2.x);
                ffma2(acc[j][1], a2, wA2.y);
                ffma2(acc[j][2], a2, wB2.x);
                ffma2(acc[j][3], a2, wB2.y);
                const ull a3 = splat2(getf(xc[j], 3));
                ffma2(acc[j][0], a3, wA3.x);
                ffma2(acc[j][1], a3, wA3.y);
                ffma2(acc[j][2], a3, wB3.x);
                ffma2(acc[j][3], a3, wB3.y);
            }
        }

        // rows 0-3 of k fully consumed -> recycle regs with next-k gather
        xc[0] = __ldcg(reinterpret_cast<const float4*>(x + (size_t)ia.x * 16) + m);
        xc[1] = __ldcg(reinterpret_cast<const float4*>(x + (size_t)ia.y * 16) + m);
        xc[2] = __ldcg(reinterpret_cast<const float4*>(x + (size_t)ia.z * 16) + m);
        xc[3] = __ldcg(reinterpret_cast<const float4*>(x + (size_t)ia.w * 16) + m);

        // idx for next-k rows 4-7
        int4 ib = *reinterpret_cast<const int4*>(idxT + kn * NPB + nlb + 4);

        // phase 3: rows 4-7 x channels jj=0,1 (reload jj01 quads)
        {
            ulonglong2 wA0 = *reinterpret_cast<const ulonglong2*>(wk);
            ulonglong2 wB0 = *reinterpret_cast<const ulonglong2*>(wk + 32);
            ulonglong2 wA1 = *reinterpret_cast<const ulonglong2*>(wk + 64);
            ulonglong2 wB1 = *reinterpret_cast<const ulonglong2*>(wk + 96);
#pragma unroll
            for (int j = 4; j < 8; ++j) {
                const ull a0 = splat2(getf(xc[j], 0));
                ffma2(acc[j][0], a0, wA0.x);
                ffma2(acc[j][1], a0, wA0.y);
                ffma2(acc[j][2], a0, wB0.x);
                ffma2(acc[j][3], a0, wB0.y);
                const ull a1 = splat2(getf(xc[j], 1));
                ffma2(acc[j][0], a1, wA1.x);
                ffma2(acc[j][1], a1, wA1.y);
                ffma2(acc[j][2], a1, wB1.x);
                ffma2(acc[j][3], a1, wB1.y);
            }
        }
        // phase 4: rows 4-7 x channels jj=2,3 (reload wA2/wB2; wA3/wB3 live)
        {
            ulonglong2 wA2 = *reinterpret_cast<const ulonglong2*>(wk + 128);
            ulonglong2 wB2 = *reinterpret_cast<const ulonglong2*>(wk + 160);
#pragma unroll
            for (int j = 4; j < 8; ++j) {
                const ull a2 = splat2(getf(xc[j], 2));
                ffma2(acc[j][0], a2, wA2.x);
                ffma2(acc[j][1], a2, wA2.y);
                ffma2(acc[j][2], a2, wB2.x);
                ffma2(acc[j][3], a2, wB2.y);
                const ull a3 = splat2(getf(xc[j], 3));
                ffma2(acc[j][0], a3, wA3.x);
                ffma2(acc[j][1], a3, wA3.y);
                ffma2(acc[j][2], a3, wB3.x);
                ffma2(acc[j][3], a3, wB3.y);
            }
        }

        // rows 4-7 consumed -> recycle with next-k gather
        xc[4] = __ldcg(reinterpret_cast<const float4*>(x + (size_t)ib.x * 16) + m);
        xc[5] = __ldcg(reinterpret_cast<const float4*>(x + (size_t)ib.y * 16) + m);
        xc[6] = __ldcg(reinterpret_cast<const float4*>(x + (size_t)ib.z * 16) + m);
        xc[7] = __ldcg(reinterpret_cast<const float4*>(x + (size_t)ib.w * 16) + m);
    }

    // Epilogue: reduce channel-quad partials over the 4 m-lanes, add bias.
    float4 b0 = __ldg(reinterpret_cast<const float4*>(bias) + 2 * h);
    float4 b1 = __ldg(reinterpret_cast<const float4*>(bias) + 2 * h + 1);
    ull bp[4] = { pack2(b0.x, b0.y), pack2(b0.z, b0.w),
                  pack2(b1.x, b1.y), pack2(b1.z, b1.w) };

#pragma unroll
    for (int j = 0; j < 8; ++j) {
#pragma unroll
        for (int p = 0; p < 4; ++p) {
            ull v = acc[j][p];
            v = addp2(v, __shfl_xor_sync(0xffffffffu, v, 1));
            v = addp2(v, __shfl_xor_sync(0xffffffffu, v, 2));
            acc[j][p] = v;
        }
        const int node = warpbase + ns * 8 + j;
        if (m == 0 && node < n_out) {
            ulonglong2* op = reinterpret_cast<ulonglong2*>(
                out + (long long)node * 16 + 8 * h);
            ulonglong2 s0; s0.x = addp2(acc[j][0], bp[0]);
                           s0.y = addp2(acc[j][1], bp[1]);
            ulonglong2 s1; s1.x = addp2(acc[j][2], bp[2]);
                           s1.y = addp2(acc[j][3], bp[3]);
            op[0] = s0;
            op[1] = s1;
        }
    }
}

extern "C" void kernel_launch(void* const* d_in, const int* in_sizes, int n_in,
                              void* d_out, int out_size)
{
    const float* x    = (const float*)d_in[0];
    const float* w    = (const float*)d_in[1];
    const float* bias = (const float*)d_in[2];
    const int*   nbr  = (const int*)d_in[3];
    const int*   lvl  = (n_in > 4) ? (const int*)d_in[4] : nullptr;

    const int n_out = in_sizes[3] / KK;
    float* out = (float*)d_out;

    const long long conv_elems = (long long)n_out * 16;
    long long tail_start = conv_elems;
    int tail_count = 0;
    if ((long long)out_size > conv_elems && lvl != nullptr)
        tail_count = (int)((long long)out_size - conv_elems);

    const int grid = (n_out + NPB - 1) / NPB;
    conv_kernel<<<grid, TPB>>>(x, w, bias, nbr, out, n_out,
                               lvl, tail_start, tail_count);
}